// round 16
// baseline (speedup 1.0000x reference)
#include <cuda_runtime.h>
#include <math.h>

typedef unsigned long long u64;
#define FULL 0xFFFFFFFFu

// ---------------- f32x2 helpers (packed fp32 FMA) ------------------------------
__device__ __forceinline__ void ffma2(u64 &d, u64 a, u64 b){
    asm("fma.rn.f32x2 %0, %1, %2, %0;" : "+l"(d) : "l"(a), "l"(b));
}
__device__ __forceinline__ u64 pk2(float a, float b){
    u64 r; asm("mov.b64 %0, {%1, %2};" : "=l"(r) : "f"(a), "f"(b)); return r;
}
__device__ __forceinline__ float2 up2(u64 v){
    float2 f; asm("mov.b64 {%0, %1}, %2;" : "=f"(f.x), "=f"(f.y) : "l"(v)); return f;
}
union F4U { float4 f; u64 u[2]; };

// ---------------- scratch (device globals; no allocs allowed) ----------------
__device__ float g_tl[(size_t)16*128*128*128];   // conv1 out low-res (n,y,x,c)      134MB
__device__ float g_r [(size_t)16*256*256*128];   // gelu out (n,h,w,c)               537MB
__device__ float g_lg[(size_t)16*32*256*256];    // conv2 logits (n,o,h,w)           134MB
__device__ float g_gx[(size_t)16*16*256*256];    // sample x coord (pixels)           67MB
__device__ float g_gy[(size_t)16*16*256*256];    // sample y coord (pixels)           67MB
__device__ float g_p1[16*256*128];               // per-(n,row) channel sums
__device__ float g_p2[16*256*128];               // per-(n,row) channel sumsq
__device__ u64   g_w2p[16*2048];                 // folded conv2 w [cp*32 + j2*8 + og*2 + t]
__device__ float g_b2[16*32];                    // folded conv2 bias

// ============ k_trconv1: fused transpose + 1x1 conv (64->128) at LOW res ========
__global__ __launch_bounds__(256) void k_trconv1(const float* __restrict__ lo,
                                                 const float* __restrict__ w1,
                                                 const float* __restrict__ bias){
    __shared__ float sa[64*129];             // acts sa[ci*129 + x]
    __shared__ __align__(16) u64 ws[2048];   // weights ws[cp*64 + oo] (64 o)
    int n = blockIdx.x >> 7, y = blockIdx.x & 127, oh = blockIdx.y;
    const float* inb = lo + ((size_t)n*64*128 + y)*128;
    for (int i = threadIdx.x; i < 2048; i += 256){
        int ci = i >> 5, x4 = (i & 31) * 4;
        float4 v = *(const float4*)(inb + (size_t)ci*16384 + x4);
        sa[ci*129 + x4] = v.x; sa[ci*129 + x4+1] = v.y;
        sa[ci*129 + x4+2] = v.z; sa[ci*129 + x4+3] = v.w;
    }
    for (int i = threadIdx.x; i < 2048; i += 256){
        int cp = i >> 6, oo = i & 63;
        int o = oh*64 + oo;
        ws[i] = pk2(__ldg(&w1[o*64 + cp*2]), __ldg(&w1[o*64 + cp*2 + 1]));
    }
    __syncthreads();
    int pxg = threadIdx.x >> 2, og = threadIdx.x & 3;   // 2 px, 16 o each
    int x0 = pxg*2;
    u64 acc[2][16];
    #pragma unroll
    for (int p = 0; p < 2; p++)
        #pragma unroll
        for (int j = 0; j < 16; j++) acc[p][j] = 0ull;
    #pragma unroll 4
    for (int ci = 0; ci < 64; ci += 2){
        int cp = ci >> 1;
        u64 a0 = pk2(sa[ci*129 + x0],     sa[(ci+1)*129 + x0]);
        u64 a1 = pk2(sa[ci*129 + x0 + 1], sa[(ci+1)*129 + x0 + 1]);
        const u64* wp = &ws[cp*64 + og*16];
        #pragma unroll
        for (int j2 = 0; j2 < 8; j2++){
            ulonglong2 wv = *(const ulonglong2*)(wp + j2*2);
            ffma2(acc[0][2*j2],   a0, wv.x); ffma2(acc[0][2*j2+1], a0, wv.y);
            ffma2(acc[1][2*j2],   a1, wv.x); ffma2(acc[1][2*j2+1], a1, wv.y);
        }
    }
    int obase = oh*64 + og*16;
    float* outb = g_tl + ((size_t)(n*128 + y)*128 + x0)*128 + obase;
    #pragma unroll
    for (int p = 0; p < 2; p++){
        float res[16];
        #pragma unroll
        for (int j = 0; j < 16; j++){
            float2 f = up2(acc[p][j]);
            res[j] = f.x + f.y + __ldg(&bias[obase + j]);
        }
        #pragma unroll
        for (int j4 = 0; j4 < 4; j4++)
            *(float4*)(outb + p*128 + j4*4) =
                make_float4(res[j4*4], res[j4*4+1], res[j4*4+2], res[j4*4+3]);
    }
}

// ============ k_up: bilinear 128->256 + exact GELU -> g_r + partial stats =======
// grid 4096 = (n, oy). x-tables hold PRE-MULTIPLIED element offsets.
__global__ __launch_bounds__(256) void k_up(){
    __shared__ int   x0s[256], x1s[256];
    __shared__ float wxs[256];
    __shared__ float sm[256];
    int n = blockIdx.x >> 8, oy = blockIdx.x & 255;
    {
        int ox = threadIdx.x;
        float xs = ox * (127.0f/255.0f);
        float xf = floorf(xs);
        int x0 = (int)xf;
        x0s[ox] = x0 * 128;
        x1s[ox] = min(x0 + 1, 127) * 128;
        wxs[ox] = xs - xf;
    }
    __syncthreads();
    float ysf = oy * (127.0f/255.0f);
    float yf  = floorf(ysf);
    int y0 = (int)yf, y1 = min(y0 + 1, 127);
    float wy = ysf - yf;
    int c = threadIdx.x & 127, half = threadIdx.x >> 7;
    const float* r0 = g_tl + ((size_t)(n*128 + y0)*128)*128 + c;
    const float* r1 = g_tl + ((size_t)(n*128 + y1)*128)*128 + c;
    float* outb = g_r + ((size_t)(n*256 + oy)*256)*128 + c;
    float s1 = 0.f, s2 = 0.f;
    #pragma unroll 4
    for (int i = 0; i < 128; i++){
        int ox = half*128 + i;
        int o0 = x0s[ox], o1 = x1s[ox]; float wx = wxs[ox];
        float a0 = __ldg(r0 + o0), a1 = __ldg(r0 + o1);
        float b0 = __ldg(r1 + o0), b1 = __ldg(r1 + o1);
        float v0 = fmaf(wx, a1 - a0, a0);
        float v1 = fmaf(wx, b1 - b0, b0);
        float v  = fmaf(wy, v1 - v0, v0);
        float ge = 0.5f*v*(1.f + erff(v*0.70710678118654752f));
        outb[(size_t)ox*128] = ge;
        s1 += ge; s2 = fmaf(ge, ge, s2);
    }
    sm[threadIdx.x] = s1; __syncthreads();
    if (half == 0) g_p1[((size_t)n*256 + oy)*128 + c] = sm[c] + sm[c+128];
    __syncthreads();
    sm[threadIdx.x] = s2; __syncthreads();
    if (half == 0) g_p2[((size_t)n*256 + oy)*128 + c] = sm[c] + sm[c+128];
}

// ============ k_fold: GN stats + SE -> folded conv2 weights (j2-interleaved) ====
__global__ __launch_bounds__(1024) void k_fold(const float* __restrict__ gnw,
        const float* __restrict__ gnb, const float* __restrict__ sw1,
        const float* __restrict__ sw2, const float* __restrict__ w2){
    int n = blockIdx.x;
    __shared__ float sc[1024];
    __shared__ float sum[128], ssq[128], mr[128], Aa[128], Bb[128], y1s[16], mu[2], inv[2];
    int c = threadIdx.x & 127, grp = threadIdx.x >> 7;
    float a = 0.f;
    for (int r = grp*32; r < grp*32 + 32; r++) a += g_p1[((size_t)n*256 + r)*128 + c];
    sc[threadIdx.x] = a; __syncthreads();
    if (threadIdx.x < 128){
        float t = 0.f;
        #pragma unroll
        for (int g = 0; g < 8; g++) t += sc[g*128 + c];
        sum[c] = t;
    }
    __syncthreads();
    a = 0.f;
    for (int r = grp*32; r < grp*32 + 32; r++) a += g_p2[((size_t)n*256 + r)*128 + c];
    sc[threadIdx.x] = a; __syncthreads();
    if (threadIdx.x < 128){
        float t = 0.f;
        #pragma unroll
        for (int g = 0; g < 8; g++) t += sc[g*128 + c];
        ssq[c] = t;
    }
    __syncthreads();
    if (threadIdx.x < 2){
        float S = 0.f, Q = 0.f;
        for (int i = 0; i < 64; i++){ S += sum[threadIdx.x*64 + i]; Q += ssq[threadIdx.x*64 + i]; }
        float mean = S * (1.f/(64.f*65536.f));
        float var  = Q * (1.f/(64.f*65536.f)) - mean*mean;
        mu[threadIdx.x] = mean; inv[threadIdx.x] = rsqrtf(var + 1e-5f);
    }
    __syncthreads();
    if (threadIdx.x < 128){
        int g = c >> 6;
        float mc = sum[c] * (1.f/65536.f);
        mr[c] = (mc - mu[g]) * inv[g] * gnw[c] + gnb[c];
    }
    __syncthreads();
    if (threadIdx.x < 16){
        float acc = 0.f;
        for (int i = 0; i < 128; i++) acc += mr[i] * sw1[threadIdx.x*128 + i];
        y1s[threadIdx.x] = fmaxf(acc, 0.f);
    }
    __syncthreads();
    if (threadIdx.x < 128){
        float t = 0.f;
        for (int j = 0; j < 16; j++) t += y1s[j] * sw2[c*16 + j];
        float sg = 1.f/(1.f + expf(-t));
        int g = c >> 6;
        Aa[c] = inv[g]*gnw[c]*sg;
        Bb[c] = (gnb[c] - mu[g]*inv[g]*gnw[c])*sg;
    }
    __syncthreads();
    // layout: g_w2p[n*2048 + cp*32 + j2*8 + og*2 + t], o = og*8 + j2*2 + t
    for (int i = threadIdx.x; i < 2048; i += 1024){
        int cp = i >> 5, r = i & 31;
        int j2 = r >> 3, og = (r >> 1) & 3, t = r & 1;
        int o = og*8 + j2*2 + t;
        int c0 = cp*2;
        g_w2p[n*2048 + i] = pk2(w2[o*128 + c0]*Aa[c0], w2[o*128 + c0 + 1]*Aa[c0 + 1]);
    }
    if (threadIdx.x < 32){
        float bb = 0.f;
        for (int i = 0; i < 128; i++) bb += w2[threadIdx.x*128 + i] * Bb[i];
        g_b2[n*32 + threadIdx.x] = bb;
    }
}

// ============ k_conv2s: smem-staged folded conv (128->32), warp=og broadcast ====
// grid 8192 = (n, oy, hx of 128px). 128 thr: og = warp (weights broadcast within
// warp), pxg = lane (acts conflict-free: 132-stride, 4l mod 32 banks per phase).
#define GE_S 132
__global__ __launch_bounds__(128) void k_conv2s(){
    extern __shared__ __align__(16) char smraw[];
    u64*   ws = (u64*)smraw;                       // [cp*32 + j2*8 + og*2 + t]
    float* ge = (float*)(smraw + 16384);           // [px*132 + c], 128 px
    float* bs = (float*)(smraw + 16384 + 128*GE_S*4);
    int b = blockIdx.x;
    int n = b >> 9, oy = (b >> 1) & 255, hx = b & 1;
    for (int i = threadIdx.x; i < 2048; i += 128) ws[i] = g_w2p[n*2048 + i];
    if (threadIdx.x < 32) bs[threadIdx.x] = g_b2[n*32 + threadIdx.x];

    // phase 1: coalesced stage of 128px x 128ch from g_r (64KB contiguous)
    const float* src = g_r + ((size_t)(n*256 + oy)*256 + hx*128)*128;
    #pragma unroll
    for (int k = 0; k < 32; k++){
        int slot = threadIdx.x + k*128;            // 4096 float4 slots
        int px = slot >> 5, c4 = (slot & 31) * 4;
        float4 v = *(const float4*)(src + (size_t)px*128 + c4);
        *(float4*)(ge + px*GE_S + c4) = v;
    }
    __syncthreads();

    // phase 2: conv 128->32; og = warp, pxg = lane; px = pxg + 32k
    int og = threadIdx.x >> 5, pxg = threadIdx.x & 31;
    u64 acc[4][8];
    #pragma unroll
    for (int k = 0; k < 4; k++)
        #pragma unroll
        for (int j = 0; j < 8; j++) acc[k][j] = 0ull;
    const float* gp = ge + pxg*GE_S;
    #pragma unroll 2
    for (int cc = 0; cc < 128; cc += 4){
        F4U a[4];
        #pragma unroll
        for (int k = 0; k < 4; k++) a[k].f = *(const float4*)(gp + k*32*GE_S + cc);
        int cp = cc >> 1;
        const u64* wp0 = ws + cp*32 + og*2;
        const u64* wp1 = ws + (cp+1)*32 + og*2;
        #pragma unroll
        for (int j2 = 0; j2 < 4; j2++){
            ulonglong2 w0 = *(const ulonglong2*)(wp0 + j2*8);   // chan pair cp
            ulonglong2 w1 = *(const ulonglong2*)(wp1 + j2*8);   // chan pair cp+1
            #pragma unroll
            for (int k = 0; k < 4; k++){
                ffma2(acc[k][2*j2],   a[k].u[0], w0.x);
                ffma2(acc[k][2*j2+1], a[k].u[0], w0.y);
                ffma2(acc[k][2*j2],   a[k].u[1], w1.x);
                ffma2(acc[k][2*j2+1], a[k].u[1], w1.y);
            }
        }
    }
    __syncthreads();
    // epilogue: stage so[px*33 + o] (reuse ge), then coalesced stores
    float* so = ge;
    #pragma unroll
    for (int k = 0; k < 4; k++)
        #pragma unroll
        for (int jj = 0; jj < 8; jj++){
            int o = og*8 + jj;
            float2 f = up2(acc[k][jj]);
            so[(pxg + k*32)*33 + o] = f.x + f.y + bs[o];
        }
    __syncthreads();
    {   // 128px x 32o: thread -> o = tid>>2, 32 px starting at (tid&3)*32
        int o = threadIdx.x >> 2, x0 = (threadIdx.x & 3) * 32;
        float* dst = g_lg + ((size_t)(n*32 + o)*256 + oy)*256 + hx*128 + x0;
        #pragma unroll
        for (int k4 = 0; k4 < 8; k4++){
            float4 r4 = make_float4(so[(x0 + k4*4    )*33 + o],
                                    so[(x0 + k4*4 + 1)*33 + o],
                                    so[(x0 + k4*4 + 2)*33 + o],
                                    so[(x0 + k4*4 + 3)*33 + o]);
            *(float4*)(dst + k4*4) = r4;
        }
    }
}

// ============ k_softx: per-row softmax+cumsum (channel 2*hd) -> gy coord ========
__global__ __launch_bounds__(256) void k_softx(){
    int lane = threadIdx.x & 31, wid = threadIdx.x >> 5;
    int R = blockIdx.x*8 + wid;
    int p = R >> 8, y = R & 255;
    int n = p >> 4, hd = p & 15;
    const float* src = g_lg + ((size_t)(n*32 + 2*hd)*256 + y)*256 + lane*8;
    float v[8];
    {
        float4 A = *(const float4*)src, B = *(const float4*)(src + 4);
        v[0]=A.x; v[1]=A.y; v[2]=A.z; v[3]=A.w;
        v[4]=B.x; v[5]=B.y; v[6]=B.z; v[7]=B.w;
    }
    float m = v[0];
    #pragma unroll
    for (int i = 1; i < 8; i++) m = fmaxf(m, v[i]);
    #pragma unroll
    for (int off = 16; off >= 1; off >>= 1) m = fmaxf(m, __shfl_xor_sync(FULL, m, off));
    float ls = 0.f;
    #pragma unroll
    for (int i = 0; i < 8; i++){ v[i] = expf(v[i] - m); ls += v[i]; }
    float pre = ls;
    #pragma unroll
    for (int off = 1; off < 32; off <<= 1){
        float t = __shfl_up_sync(FULL, pre, off);
        if (lane >= off) pre += t;
    }
    float total = __shfl_sync(FULL, pre, 31);
    float run = pre - ls;
    float sc = 255.f / total;
    float o[8];
    #pragma unroll
    for (int i = 0; i < 8; i++){ run += v[i]; o[i] = run * sc; }
    float* dst = g_gy + (size_t)p*65536 + y*256 + lane*8;
    *(float4*)dst       = make_float4(o[0], o[1], o[2], o[3]);
    *(float4*)(dst + 4) = make_float4(o[4], o[5], o[6], o[7]);
}

// ============ k_softy: per-col softmax+cumsum, 4 row-chunks x 1024 thr ==========
__global__ __launch_bounds__(1024) void k_softy(){
    __shared__ float pm[4][256], ps[4][256];
    int pb = blockIdx.x;
    int n = pb >> 4, hd = pb & 15;
    int col = threadIdx.x & 255, ch = threadIdx.x >> 8;
    const float* src = g_lg + ((size_t)(n*32 + 2*hd + 1)*256)*256 + col;
    float m = -1e30f;
    for (int y = ch*64; y < ch*64 + 64; y++) m = fmaxf(m, __ldg(src + (size_t)y*256));
    pm[ch][col] = m; __syncthreads();
    m = fmaxf(fmaxf(pm[0][col], pm[1][col]), fmaxf(pm[2][col], pm[3][col]));
    float s = 0.f;
    for (int y = ch*64; y < ch*64 + 64; y++) s += expf(__ldg(src + (size_t)y*256) - m);
    ps[ch][col] = s; __syncthreads();
    float tot = ps[0][col] + ps[1][col] + ps[2][col] + ps[3][col];
    float run = 0.f;
    for (int k = 0; k < 4; k++) if (k < ch) run += ps[k][col];
    float sc = 255.f / tot;
    float* dst = g_gx + (size_t)pb*65536 + col;
    for (int y = ch*64; y < ch*64 + 64; y++){
        run += expf(__ldg(src + (size_t)y*256) - m);
        dst[(size_t)y*256] = run * sc;
    }
}

// ============ k_sample: 32x32 tiles, lanes along y (coalesced gathers) ==========
__global__ __launch_bounds__(256) void k_sample(const float* __restrict__ hi,
                                                float* __restrict__ out){
    __shared__ float sgx[32][33], sgy[32][33], so[32][33];
    int b = blockIdx.x;
    int p = b >> 6, tile = b & 63;
    int y0 = (tile >> 3) * 32, x0 = (tile & 7) * 32;
    size_t base = (size_t)p*65536;
    {
        int row = threadIdx.x >> 3, c4 = (threadIdx.x & 7) * 4;
        size_t idx = base + (size_t)(y0 + row)*256 + x0 + c4;
        float4 a = *(const float4*)(g_gx + idx);
        float4 c = *(const float4*)(g_gy + idx);
        sgx[row][c4]=a.x; sgx[row][c4+1]=a.y; sgx[row][c4+2]=a.z; sgx[row][c4+3]=a.w;
        sgy[row][c4]=c.x; sgy[row][c4+1]=c.y; sgy[row][c4+2]=c.z; sgy[row][c4+3]=c.w;
    }
    __syncthreads();
    const float* s = hi + base;
    int yl = threadIdx.x & 31, xg = threadIdx.x >> 5;
    #pragma unroll
    for (int k = 0; k < 4; k++){
        int xl = xg*4 + k;
        float gx = sgx[yl][xl], gy = sgy[yl][xl];
        float xf = floorf(gx), yf = floorf(gy);
        float wx = gx - xf, wy = gy - yf;
        int ix0 = (int)xf, iy0 = (int)yf;
        int ix1 = ix0 + 1, iy1 = iy0 + 1;
        float mx0 = (ix0 >= 0 && ix0 <= 255) ? 1.f : 0.f;
        float mx1 = (ix1 >= 0 && ix1 <= 255) ? 1.f : 0.f;
        float my0 = (iy0 >= 0 && iy0 <= 255) ? 1.f : 0.f;
        float my1 = (iy1 >= 0 && iy1 <= 255) ? 1.f : 0.f;
        int cx0 = min(max(ix0, 0), 255), cx1 = min(max(ix1, 0), 255);
        int cy0 = min(max(iy0, 0), 255), cy1 = min(max(iy1, 0), 255);
        float v00 = __ldg(s + (size_t)cy0*256 + cx0);
        float v10 = __ldg(s + (size_t)cy0*256 + cx1);
        float v01 = __ldg(s + (size_t)cy1*256 + cx0);
        float v11 = __ldg(s + (size_t)cy1*256 + cx1);
        so[yl][xl] = v00*((1.f-wx)*(1.f-wy)*mx0*my0)
                   + v10*(wx*(1.f-wy)*mx1*my0)
                   + v01*((1.f-wx)*wy*mx0*my1)
                   + v11*(wx*wy*mx1*my1);
    }
    __syncthreads();
    {
        int row = threadIdx.x >> 3, c4 = (threadIdx.x & 7) * 4;
        size_t idx = base + (size_t)(y0 + row)*256 + x0 + c4;
        *(float4*)(out + idx) = make_float4(so[row][c4], so[row][c4+1],
                                            so[row][c4+2], so[row][c4+3]);
    }
}

// ================================ launch ========================================
extern "C" void kernel_launch(void* const* d_in, const int* in_sizes, int n_in,
                              void* d_out, int out_size){
    const float* lowres  = (const float*)d_in[0];
    const float* highres = (const float*)d_in[1];
    const float* conv1_w = (const float*)d_in[2];
    const float* conv1_b = (const float*)d_in[3];
    const float* gn_w    = (const float*)d_in[4];
    const float* gn_b    = (const float*)d_in[5];
    const float* se_w1   = (const float*)d_in[6];
    const float* se_w2   = (const float*)d_in[7];
    const float* conv2_w = (const float*)d_in[8];
    float* out = (float*)d_out;

    const int c2_smem = 16384 + 128*GE_S*4 + 128;   // ws + tile + bs = 84096B
    cudaFuncSetAttribute(k_conv2s, cudaFuncAttributeMaxDynamicSharedMemorySize, c2_smem);

    k_trconv1<<<dim3(2048, 2), 256>>>(lowres, conv1_w, conv1_b);  // 1
    k_up     <<<4096, 256>>>();                                   // 2
    k_fold   <<<16, 1024>>>(gn_w, gn_b, se_w1, se_w2, conv2_w);   // 3
    k_conv2s <<<8192, 128, c2_smem>>>();                          // 4  <- profiled
    k_softx  <<<8192, 256>>>();                                   // 5
    k_softy  <<<256, 1024>>>();                                   // 6
    k_sample <<<16384, 256>>>(highres, out);                      // 7
}

// round 17
// speedup vs baseline: 1.0934x; 1.0934x over previous
#include <cuda_runtime.h>
#include <math.h>

typedef unsigned long long u64;
#define FULL 0xFFFFFFFFu

// ---------------- f32x2 helpers (packed fp32 FMA) ------------------------------
__device__ __forceinline__ void ffma2(u64 &d, u64 a, u64 b){
    asm("fma.rn.f32x2 %0, %1, %2, %0;" : "+l"(d) : "l"(a), "l"(b));
}
__device__ __forceinline__ u64 pk2(float a, float b){
    u64 r; asm("mov.b64 %0, {%1, %2};" : "=l"(r) : "f"(a), "f"(b)); return r;
}
__device__ __forceinline__ float2 up2(u64 v){
    float2 f; asm("mov.b64 {%0, %1}, %2;" : "=f"(f.x), "=f"(f.y) : "l"(v)); return f;
}
union F4U { float4 f; u64 u[2]; };

// ---------------- scratch (device globals; no allocs allowed) ----------------
__device__ float g_tl[(size_t)16*128*128*128];   // conv1 out low-res (n,y,x,c)      134MB
__device__ float g_r [(size_t)16*256*256*128];   // gelu out (n,h,w,c)               537MB
__device__ float g_lg[(size_t)16*32*256*256];    // conv2 logits (n,o,h,w)           134MB
__device__ float g_gx[(size_t)16*16*256*256];    // sample x coord (pixels)           67MB
__device__ float g_gy[(size_t)16*16*256*256];    // sample y coord (pixels)           67MB
__device__ float g_p1[16*256*128];               // per-(n,row) channel sums
__device__ float g_p2[16*256*128];               // per-(n,row) channel sumsq
__device__ u64   g_w2p[16*2048];                 // folded conv2 w [cp*32 + j2*8 + og*2 + t]
__device__ float g_b2[16*32];                    // folded conv2 bias

// ============ k_trconv1: fused transpose + 1x1 conv (64->128) at LOW res ========
__global__ __launch_bounds__(256) void k_trconv1(const float* __restrict__ lo,
                                                 const float* __restrict__ w1,
                                                 const float* __restrict__ bias){
    __shared__ float sa[64*129];             // acts sa[ci*129 + x]
    __shared__ __align__(16) u64 ws[2048];   // weights ws[cp*64 + oo] (64 o)
    int n = blockIdx.x >> 7, y = blockIdx.x & 127, oh = blockIdx.y;
    const float* inb = lo + ((size_t)n*64*128 + y)*128;
    for (int i = threadIdx.x; i < 2048; i += 256){
        int ci = i >> 5, x4 = (i & 31) * 4;
        float4 v = *(const float4*)(inb + (size_t)ci*16384 + x4);
        sa[ci*129 + x4] = v.x; sa[ci*129 + x4+1] = v.y;
        sa[ci*129 + x4+2] = v.z; sa[ci*129 + x4+3] = v.w;
    }
    for (int i = threadIdx.x; i < 2048; i += 256){
        int cp = i >> 6, oo = i & 63;
        int o = oh*64 + oo;
        ws[i] = pk2(__ldg(&w1[o*64 + cp*2]), __ldg(&w1[o*64 + cp*2 + 1]));
    }
    __syncthreads();
    int pxg = threadIdx.x >> 2, og = threadIdx.x & 3;   // 2 px, 16 o each
    int x0 = pxg*2;
    u64 acc[2][16];
    #pragma unroll
    for (int p = 0; p < 2; p++)
        #pragma unroll
        for (int j = 0; j < 16; j++) acc[p][j] = 0ull;
    #pragma unroll 4
    for (int ci = 0; ci < 64; ci += 2){
        int cp = ci >> 1;
        u64 a0 = pk2(sa[ci*129 + x0],     sa[(ci+1)*129 + x0]);
        u64 a1 = pk2(sa[ci*129 + x0 + 1], sa[(ci+1)*129 + x0 + 1]);
        const u64* wp = &ws[cp*64 + og*16];
        #pragma unroll
        for (int j2 = 0; j2 < 8; j2++){
            ulonglong2 wv = *(const ulonglong2*)(wp + j2*2);
            ffma2(acc[0][2*j2],   a0, wv.x); ffma2(acc[0][2*j2+1], a0, wv.y);
            ffma2(acc[1][2*j2],   a1, wv.x); ffma2(acc[1][2*j2+1], a1, wv.y);
        }
    }
    int obase = oh*64 + og*16;
    float* outb = g_tl + ((size_t)(n*128 + y)*128 + x0)*128 + obase;
    #pragma unroll
    for (int p = 0; p < 2; p++){
        float res[16];
        #pragma unroll
        for (int j = 0; j < 16; j++){
            float2 f = up2(acc[p][j]);
            res[j] = f.x + f.y + __ldg(&bias[obase + j]);
        }
        #pragma unroll
        for (int j4 = 0; j4 < 4; j4++)
            *(float4*)(outb + p*128 + j4*4) =
                make_float4(res[j4*4], res[j4*4+1], res[j4*4+2], res[j4*4+3]);
    }
}

// ============ k_up: bilinear 128->256 + exact GELU -> g_r + partial stats =======
__global__ __launch_bounds__(256) void k_up(){
    __shared__ int   x0s[256], x1s[256];
    __shared__ float wxs[256];
    __shared__ float sm[256];
    int n = blockIdx.x >> 8, oy = blockIdx.x & 255;
    {
        int ox = threadIdx.x;
        float xs = ox * (127.0f/255.0f);
        float xf = floorf(xs);
        int x0 = (int)xf;
        x0s[ox] = x0 * 128;
        x1s[ox] = min(x0 + 1, 127) * 128;
        wxs[ox] = xs - xf;
    }
    __syncthreads();
    float ysf = oy * (127.0f/255.0f);
    float yf  = floorf(ysf);
    int y0 = (int)yf, y1 = min(y0 + 1, 127);
    float wy = ysf - yf;
    int c = threadIdx.x & 127, half = threadIdx.x >> 7;
    const float* r0 = g_tl + ((size_t)(n*128 + y0)*128)*128 + c;
    const float* r1 = g_tl + ((size_t)(n*128 + y1)*128)*128 + c;
    float* outb = g_r + ((size_t)(n*256 + oy)*256)*128 + c;
    float s1 = 0.f, s2 = 0.f;
    #pragma unroll 4
    for (int i = 0; i < 128; i++){
        int ox = half*128 + i;
        int o0 = x0s[ox], o1 = x1s[ox]; float wx = wxs[ox];
        float a0 = __ldg(r0 + o0), a1 = __ldg(r0 + o1);
        float b0 = __ldg(r1 + o0), b1 = __ldg(r1 + o1);
        float v0 = fmaf(wx, a1 - a0, a0);
        float v1 = fmaf(wx, b1 - b0, b0);
        float v  = fmaf(wy, v1 - v0, v0);
        float ge = 0.5f*v*(1.f + erff(v*0.70710678118654752f));
        outb[(size_t)ox*128] = ge;
        s1 += ge; s2 = fmaf(ge, ge, s2);
    }
    sm[threadIdx.x] = s1; __syncthreads();
    if (half == 0) g_p1[((size_t)n*256 + oy)*128 + c] = sm[c] + sm[c+128];
    __syncthreads();
    sm[threadIdx.x] = s2; __syncthreads();
    if (half == 0) g_p2[((size_t)n*256 + oy)*128 + c] = sm[c] + sm[c+128];
}

// ============ k_fold: GN stats + SE -> folded conv2 weights (j2-interleaved) ====
__global__ __launch_bounds__(1024) void k_fold(const float* __restrict__ gnw,
        const float* __restrict__ gnb, const float* __restrict__ sw1,
        const float* __restrict__ sw2, const float* __restrict__ w2){
    int n = blockIdx.x;
    __shared__ float sc[1024];
    __shared__ float sum[128], ssq[128], mr[128], Aa[128], Bb[128], y1s[16], mu[2], inv[2];
    int c = threadIdx.x & 127, grp = threadIdx.x >> 7;
    float a = 0.f;
    for (int r = grp*32; r < grp*32 + 32; r++) a += g_p1[((size_t)n*256 + r)*128 + c];
    sc[threadIdx.x] = a; __syncthreads();
    if (threadIdx.x < 128){
        float t = 0.f;
        #pragma unroll
        for (int g = 0; g < 8; g++) t += sc[g*128 + c];
        sum[c] = t;
    }
    __syncthreads();
    a = 0.f;
    for (int r = grp*32; r < grp*32 + 32; r++) a += g_p2[((size_t)n*256 + r)*128 + c];
    sc[threadIdx.x] = a; __syncthreads();
    if (threadIdx.x < 128){
        float t = 0.f;
        #pragma unroll
        for (int g = 0; g < 8; g++) t += sc[g*128 + c];
        ssq[c] = t;
    }
    __syncthreads();
    if (threadIdx.x < 2){
        float S = 0.f, Q = 0.f;
        for (int i = 0; i < 64; i++){ S += sum[threadIdx.x*64 + i]; Q += ssq[threadIdx.x*64 + i]; }
        float mean = S * (1.f/(64.f*65536.f));
        float var  = Q * (1.f/(64.f*65536.f)) - mean*mean;
        mu[threadIdx.x] = mean; inv[threadIdx.x] = rsqrtf(var + 1e-5f);
    }
    __syncthreads();
    if (threadIdx.x < 128){
        int g = c >> 6;
        float mc = sum[c] * (1.f/65536.f);
        mr[c] = (mc - mu[g]) * inv[g] * gnw[c] + gnb[c];
    }
    __syncthreads();
    if (threadIdx.x < 16){
        float acc = 0.f;
        for (int i = 0; i < 128; i++) acc += mr[i] * sw1[threadIdx.x*128 + i];
        y1s[threadIdx.x] = fmaxf(acc, 0.f);
    }
    __syncthreads();
    if (threadIdx.x < 128){
        float t = 0.f;
        for (int j = 0; j < 16; j++) t += y1s[j] * sw2[c*16 + j];
        float sg = 1.f/(1.f + expf(-t));
        int g = c >> 6;
        Aa[c] = inv[g]*gnw[c]*sg;
        Bb[c] = (gnb[c] - mu[g]*inv[g]*gnw[c])*sg;
    }
    __syncthreads();
    // layout: g_w2p[n*2048 + cp*32 + j2*8 + og*2 + t], o = og*8 + j2*2 + t
    for (int i = threadIdx.x; i < 2048; i += 1024){
        int cp = i >> 5, r = i & 31;
        int j2 = r >> 3, og = (r >> 1) & 3, t = r & 1;
        int o = og*8 + j2*2 + t;
        int c0 = cp*2;
        g_w2p[n*2048 + i] = pk2(w2[o*128 + c0]*Aa[c0], w2[o*128 + c0 + 1]*Aa[c0 + 1]);
    }
    if (threadIdx.x < 32){
        float bb = 0.f;
        for (int i = 0; i < 128; i++) bb += w2[threadIdx.x*128 + i] * Bb[i];
        g_b2[n*32 + threadIdx.x] = bb;
    }
}

// ============ k_conv2s: smem-staged folded conv (128->32), 256 thr, 2 px/thread =
// grid 8192 = (n, oy, hx of 128px). 8 warps: og = wid&3 (weights broadcast within
// warp), pxg = (wid>>2)*32 + lane (acts conflict-free per 8-lane phase).
#define GE_S 132
__global__ __launch_bounds__(256) void k_conv2s(){
    extern __shared__ __align__(16) char smraw[];
    u64*   ws = (u64*)smraw;                       // [cp*32 + j2*8 + og*2 + t]
    float* ge = (float*)(smraw + 16384);           // [px*132 + c], 128 px
    float* bs = (float*)(smraw + 16384 + 128*GE_S*4);
    int b = blockIdx.x;
    int n = b >> 9, oy = (b >> 1) & 255, hx = b & 1;
    for (int i = threadIdx.x; i < 2048; i += 256) ws[i] = g_w2p[n*2048 + i];
    if (threadIdx.x < 32) bs[threadIdx.x] = g_b2[n*32 + threadIdx.x];

    // phase 1: coalesced stage of 128px x 128ch from g_r (64KB contiguous)
    const float* src = g_r + ((size_t)(n*256 + oy)*256 + hx*128)*128;
    #pragma unroll
    for (int k = 0; k < 16; k++){
        int slot = threadIdx.x + k*256;            // 4096 float4 slots
        int px = slot >> 5, c4 = (slot & 31) * 4;
        float4 v = *(const float4*)(src + (size_t)px*128 + c4);
        *(float4*)(ge + px*GE_S + c4) = v;
    }
    __syncthreads();

    // phase 2: conv 128->32; og = wid&3, pxg = (wid>>2)*32+lane; px = pxg + 64k
    int wid = threadIdx.x >> 5, lane = threadIdx.x & 31;
    int og = wid & 3, pxg = (wid >> 2)*32 + lane;   // 0..63
    u64 acc[2][8];
    #pragma unroll
    for (int k = 0; k < 2; k++)
        #pragma unroll
        for (int j = 0; j < 8; j++) acc[k][j] = 0ull;
    const float* gp = ge + pxg*GE_S;
    #pragma unroll 2
    for (int cc = 0; cc < 128; cc += 4){
        F4U a[2];
        a[0].f = *(const float4*)(gp + cc);
        a[1].f = *(const float4*)(gp + 64*GE_S + cc);
        int cp = cc >> 1;
        const u64* wp0 = ws + cp*32 + og*2;
        const u64* wp1 = ws + (cp+1)*32 + og*2;
        #pragma unroll
        for (int j2 = 0; j2 < 4; j2++){
            ulonglong2 w0 = *(const ulonglong2*)(wp0 + j2*8);   // chan pair cp
            ulonglong2 w1 = *(const ulonglong2*)(wp1 + j2*8);   // chan pair cp+1
            #pragma unroll
            for (int k = 0; k < 2; k++){
                ffma2(acc[k][2*j2],   a[k].u[0], w0.x);
                ffma2(acc[k][2*j2+1], a[k].u[0], w0.y);
                ffma2(acc[k][2*j2],   a[k].u[1], w1.x);
                ffma2(acc[k][2*j2+1], a[k].u[1], w1.y);
            }
        }
    }
    __syncthreads();
    // epilogue: stage so[px*33 + o] (reuse ge), then coalesced stores
    float* so = ge;
    #pragma unroll
    for (int k = 0; k < 2; k++)
        #pragma unroll
        for (int jj = 0; jj < 8; jj++){
            int o = og*8 + jj;
            float2 f = up2(acc[k][jj]);
            so[(pxg + k*64)*33 + o] = f.x + f.y + bs[o];
        }
    __syncthreads();
    {   // 128px x 32o = 1024 float4 slots; thread -> o = tid>>3, 16px at (tid&7)*16
        int o = threadIdx.x >> 3, x16 = (threadIdx.x & 7) * 16;
        float* dst = g_lg + ((size_t)(n*32 + o)*256 + oy)*256 + hx*128 + x16;
        #pragma unroll
        for (int k4 = 0; k4 < 4; k4++){
            float4 r4 = make_float4(so[(x16 + k4*4    )*33 + o],
                                    so[(x16 + k4*4 + 1)*33 + o],
                                    so[(x16 + k4*4 + 2)*33 + o],
                                    so[(x16 + k4*4 + 3)*33 + o]);
            *(float4*)(dst + k4*4) = r4;
        }
    }
}

// ============ k_softx: per-row softmax+cumsum (channel 2*hd) -> gy coord ========
__global__ __launch_bounds__(256) void k_softx(){
    int lane = threadIdx.x & 31, wid = threadIdx.x >> 5;
    int R = blockIdx.x*8 + wid;
    int p = R >> 8, y = R & 255;
    int n = p >> 4, hd = p & 15;
    const float* src = g_lg + ((size_t)(n*32 + 2*hd)*256 + y)*256 + lane*8;
    float v[8];
    {
        float4 A = *(const float4*)src, B = *(const float4*)(src + 4);
        v[0]=A.x; v[1]=A.y; v[2]=A.z; v[3]=A.w;
        v[4]=B.x; v[5]=B.y; v[6]=B.z; v[7]=B.w;
    }
    float m = v[0];
    #pragma unroll
    for (int i = 1; i < 8; i++) m = fmaxf(m, v[i]);
    #pragma unroll
    for (int off = 16; off >= 1; off >>= 1) m = fmaxf(m, __shfl_xor_sync(FULL, m, off));
    float ls = 0.f;
    #pragma unroll
    for (int i = 0; i < 8; i++){ v[i] = expf(v[i] - m); ls += v[i]; }
    float pre = ls;
    #pragma unroll
    for (int off = 1; off < 32; off <<= 1){
        float t = __shfl_up_sync(FULL, pre, off);
        if (lane >= off) pre += t;
    }
    float total = __shfl_sync(FULL, pre, 31);
    float run = pre - ls;
    float sc = 255.f / total;
    float o[8];
    #pragma unroll
    for (int i = 0; i < 8; i++){ run += v[i]; o[i] = run * sc; }
    float* dst = g_gy + (size_t)p*65536 + y*256 + lane*8;
    *(float4*)dst       = make_float4(o[0], o[1], o[2], o[3]);
    *(float4*)(dst + 4) = make_float4(o[4], o[5], o[6], o[7]);
}

// ============ k_softy: per-col softmax+cumsum, 4 row-chunks x 1024 thr ==========
__global__ __launch_bounds__(1024) void k_softy(){
    __shared__ float pm[4][256], ps[4][256];
    int pb = blockIdx.x;
    int n = pb >> 4, hd = pb & 15;
    int col = threadIdx.x & 255, ch = threadIdx.x >> 8;
    const float* src = g_lg + ((size_t)(n*32 + 2*hd + 1)*256)*256 + col;
    float m = -1e30f;
    for (int y = ch*64; y < ch*64 + 64; y++) m = fmaxf(m, __ldg(src + (size_t)y*256));
    pm[ch][col] = m; __syncthreads();
    m = fmaxf(fmaxf(pm[0][col], pm[1][col]), fmaxf(pm[2][col], pm[3][col]));
    float s = 0.f;
    for (int y = ch*64; y < ch*64 + 64; y++) s += expf(__ldg(src + (size_t)y*256) - m);
    ps[ch][col] = s; __syncthreads();
    float tot = ps[0][col] + ps[1][col] + ps[2][col] + ps[3][col];
    float run = 0.f;
    for (int k = 0; k < 4; k++) if (k < ch) run += ps[k][col];
    float sc = 255.f / tot;
    float* dst = g_gx + (size_t)pb*65536 + col;
    for (int y = ch*64; y < ch*64 + 64; y++){
        run += expf(__ldg(src + (size_t)y*256) - m);
        dst[(size_t)y*256] = run * sc;
    }
}

// ============ k_sample: 32x32 tiles, lanes along y (coalesced gathers) ==========
__global__ __launch_bounds__(256) void k_sample(const float* __restrict__ hi,
                                                float* __restrict__ out){
    __shared__ float sgx[32][33], sgy[32][33], so[32][33];
    int b = blockIdx.x;
    int p = b >> 6, tile = b & 63;
    int y0 = (tile >> 3) * 32, x0 = (tile & 7) * 32;
    size_t base = (size_t)p*65536;
    {
        int row = threadIdx.x >> 3, c4 = (threadIdx.x & 7) * 4;
        size_t idx = base + (size_t)(y0 + row)*256 + x0 + c4;
        float4 a = *(const float4*)(g_gx + idx);
        float4 c = *(const float4*)(g_gy + idx);
        sgx[row][c4]=a.x; sgx[row][c4+1]=a.y; sgx[row][c4+2]=a.z; sgx[row][c4+3]=a.w;
        sgy[row][c4]=c.x; sgy[row][c4+1]=c.y; sgy[row][c4+2]=c.z; sgy[row][c4+3]=c.w;
    }
    __syncthreads();
    const float* s = hi + base;
    int yl = threadIdx.x & 31, xg = threadIdx.x >> 5;
    #pragma unroll
    for (int k = 0; k < 4; k++){
        int xl = xg*4 + k;
        float gx = sgx[yl][xl], gy = sgy[yl][xl];
        float xf = floorf(gx), yf = floorf(gy);
        float wx = gx - xf, wy = gy - yf;
        int ix0 = (int)xf, iy0 = (int)yf;
        int ix1 = ix0 + 1, iy1 = iy0 + 1;
        float mx0 = (ix0 >= 0 && ix0 <= 255) ? 1.f : 0.f;
        float mx1 = (ix1 >= 0 && ix1 <= 255) ? 1.f : 0.f;
        float my0 = (iy0 >= 0 && iy0 <= 255) ? 1.f : 0.f;
        float my1 = (iy1 >= 0 && iy1 <= 255) ? 1.f : 0.f;
        int cx0 = min(max(ix0, 0), 255), cx1 = min(max(ix1, 0), 255);
        int cy0 = min(max(iy0, 0), 255), cy1 = min(max(iy1, 0), 255);
        float v00 = __ldg(s + (size_t)cy0*256 + cx0);
        float v10 = __ldg(s + (size_t)cy0*256 + cx1);
        float v01 = __ldg(s + (size_t)cy1*256 + cx0);
        float v11 = __ldg(s + (size_t)cy1*256 + cx1);
        so[yl][xl] = v00*((1.f-wx)*(1.f-wy)*mx0*my0)
                   + v10*(wx*(1.f-wy)*mx1*my0)
                   + v01*((1.f-wx)*wy*mx0*my1)
                   + v11*(wx*wy*mx1*my1);
    }
    __syncthreads();
    {
        int row = threadIdx.x >> 3, c4 = (threadIdx.x & 7) * 4;
        size_t idx = base + (size_t)(y0 + row)*256 + x0 + c4;
        *(float4*)(out + idx) = make_float4(so[row][c4], so[row][c4+1],
                                            so[row][c4+2], so[row][c4+3]);
    }
}

// ================================ launch ========================================
extern "C" void kernel_launch(void* const* d_in, const int* in_sizes, int n_in,
                              void* d_out, int out_size){
    const float* lowres  = (const float*)d_in[0];
    const float* highres = (const float*)d_in[1];
    const float* conv1_w = (const float*)d_in[2];
    const float* conv1_b = (const float*)d_in[3];
    const float* gn_w    = (const float*)d_in[4];
    const float* gn_b    = (const float*)d_in[5];
    const float* se_w1   = (const float*)d_in[6];
    const float* se_w2   = (const float*)d_in[7];
    const float* conv2_w = (const float*)d_in[8];
    float* out = (float*)d_out;

    const int c2_smem = 16384 + 128*GE_S*4 + 128;   // ws + tile + bs = 84096B
    cudaFuncSetAttribute(k_conv2s, cudaFuncAttributeMaxDynamicSharedMemorySize, c2_smem);

    k_trconv1<<<dim3(2048, 2), 256>>>(lowres, conv1_w, conv1_b);  // 1
    k_up     <<<4096, 256>>>();                                   // 2
    k_fold   <<<16, 1024>>>(gn_w, gn_b, se_w1, se_w2, conv2_w);   // 3
    k_conv2s <<<8192, 256, c2_smem>>>();                          // 4  <- profiled
    k_softx  <<<8192, 256>>>();                                   // 5
    k_softy  <<<256, 1024>>>();                                   // 6
    k_sample <<<16384, 256>>>(highres, out);                      // 7
}